// round 2
// baseline (speedup 1.0000x reference)
#include <cuda_runtime.h>
#include <cuda_bf16.h>
#include <cstdint>

// ============================================================================
// BinaryToCost: out[i] = x_i @ Q @ x_i  (x: 1024x2048 {0,1} fp32, Q: 2048^2 fp32)
// Split-precision bf16 mma.sync GEMM (Q = Qhi + Qlo), fused masked row-reduce.
// Base-target sm_103 only: mma.sync + ldmatrix + cp.async (no tcgen05).
// ============================================================================

#define NDIM 2048
#define BDIM 1024
#define BM 128
#define BN 128
#define BK 64            // K elements per chunk (= 128B rows, SW128 atom)
#define NCHUNK 64        // 32 chunks Qhi + 32 chunks Qlo
#define NT (NDIM / BN)   // 16
#define MT (BDIM / BM)   // 8
#define STAGE_BYTES 32768  // A(16KB) + B(16KB)
#define SMEM_BYTES (2 * STAGE_BYTES)

// ---------------------------------------------------------------------------
__device__ __align__(16) __nv_bfloat16 g_xh[BDIM * NDIM];    // bf16(x)      [m][k]
__device__ __align__(16) __nv_bfloat16 g_qhiT[NDIM * NDIM];  // bf16(Q)^T    [n][k]
__device__ __align__(16) __nv_bfloat16 g_qloT[NDIM * NDIM];  // bf16 resid^T [n][k]
__device__ float g_partial[NT * BDIM];

// ---------------------------------------------------------------------------
__device__ __forceinline__ uint32_t smem_u32(const void* p) {
    return (uint32_t)__cvta_generic_to_shared(p);
}
__device__ __forceinline__ uint32_t sw128(uint32_t off) {
    return off ^ ((off >> 3) & 0x70);
}
__device__ __forceinline__ void cp_async16(uint32_t dst, const void* src) {
    asm volatile("cp.async.cg.shared.global [%0], [%1], 16;"
                 :: "r"(dst), "l"(src) : "memory");
}

#define LDSM_X4(r, addr)                                                      \
    asm volatile("ldmatrix.sync.aligned.m8n8.x4.shared.b16 {%0,%1,%2,%3}, [%4];" \
                 : "=r"((r)[0]), "=r"((r)[1]), "=r"((r)[2]), "=r"((r)[3])     \
                 : "r"(addr))

__device__ __forceinline__ void mma16816(float* d, const uint32_t* a,
                                         const uint32_t* b) {
    asm volatile(
        "mma.sync.aligned.m16n8k16.row.col.f32.bf16.bf16.f32 "
        "{%0,%1,%2,%3}, {%4,%5,%6,%7}, {%8,%9}, {%0,%1,%2,%3};"
        : "+f"(d[0]), "+f"(d[1]), "+f"(d[2]), "+f"(d[3])
        : "r"(a[0]), "r"(a[1]), "r"(a[2]), "r"(a[3]), "r"(b[0]), "r"(b[1]));
}

// ---------------------------------------------------------------------------
// Prep kernels
// ---------------------------------------------------------------------------
__global__ void k_prep_x(const float* __restrict__ x) {
    int i = blockIdx.x * blockDim.x + threadIdx.x;
    float4 v = reinterpret_cast<const float4*>(x)[i];
    __nv_bfloat162* o = reinterpret_cast<__nv_bfloat162*>(g_xh);
    o[2 * i + 0] = __floats2bfloat162_rn(v.x, v.y);
    o[2 * i + 1] = __floats2bfloat162_rn(v.z, v.w);
}

__global__ void k_prep_q(const float* __restrict__ Q) {
    __shared__ float tile[32][33];
    int bx = blockIdx.x * 32;  // n base
    int by = blockIdx.y * 32;  // k base
    int tx = threadIdx.x, ty = threadIdx.y;  // 32 x 8
#pragma unroll
    for (int i = 0; i < 32; i += 8)
        tile[ty + i][tx] = Q[(by + ty + i) * NDIM + bx + tx];
    __syncthreads();
#pragma unroll
    for (int i = 0; i < 32; i += 8) {
        float v = tile[tx][ty + i];
        __nv_bfloat16 h = __float2bfloat16(v);
        float lo = v - __bfloat162float(h);
        int n = bx + ty + i;
        int k = by + tx;
        g_qhiT[n * NDIM + k] = h;
        g_qloT[n * NDIM + k] = __float2bfloat16(lo);
    }
}

// ---------------------------------------------------------------------------
// GEMM + fused masked row-reduce.  grid (NT, MT), 256 threads (8 warps).
// Warp tile 64x32: warps 2(M) x 4(N); per warp 4 m16 x 4 n8 mma tiles.
// ---------------------------------------------------------------------------
__global__ void __launch_bounds__(256, 1)
k_gemm(const float* __restrict__ x) {
    extern __shared__ __align__(1024) uint8_t smem[];

    const int tid = threadIdx.x;
    const int wid = tid >> 5;
    const int lane = tid & 31;
    const int n0 = blockIdx.x * BN;
    const int m0 = blockIdx.y * BM;
    const int wm = (wid >> 2) * 64;  // warp m-offset in tile
    const int wn = (wid & 3) * 32;   // warp n-offset in tile
    const int grp = lane >> 3;       // ldmatrix 8x8 quadrant
    const int ri = lane & 7;

    // cp.async staging map: 1024 16B-granules per 16KB tile, 4 per thread
    int rr[4], cc[4];
#pragma unroll
    for (int i = 0; i < 4; ++i) {
        int g = tid + 256 * i;
        rr[i] = g >> 3;
        cc[i] = g & 7;
    }

    auto stage_load = [&](int c, int buf) {
        uint32_t sa = smem_u32(smem + buf * STAGE_BYTES);
        uint32_t sb = sa + 16384;
        int kbE = (c & 31) * BK;
        const __nv_bfloat16* qs = (c < 32) ? g_qhiT : g_qloT;
#pragma unroll
        for (int i = 0; i < 4; ++i) {
            uint32_t off = sw128((uint32_t)(rr[i] * 128 + cc[i] * 16));
            cp_async16(sa + off, g_xh + (m0 + rr[i]) * NDIM + kbE + cc[i] * 8);
            cp_async16(sb + off, qs + (n0 + rr[i]) * NDIM + kbE + cc[i] * 8);
        }
        asm volatile("cp.async.commit_group;" ::: "memory");
    };

    float cfrag[4][4][4];
#pragma unroll
    for (int mt = 0; mt < 4; ++mt)
#pragma unroll
        for (int nt = 0; nt < 4; ++nt)
#pragma unroll
            for (int r = 0; r < 4; ++r) cfrag[mt][nt][r] = 0.0f;

    stage_load(0, 0);
    stage_load(1, 1);

    for (int ch = 0; ch < NCHUNK; ++ch) {
        if (ch == NCHUNK - 1)
            asm volatile("cp.async.wait_group 0;" ::: "memory");
        else
            asm volatile("cp.async.wait_group 1;" ::: "memory");
        __syncthreads();

        const int buf = ch & 1;
        const uint32_t sa = smem_u32(smem + buf * STAGE_BYTES);
        const uint32_t sb = sa + 16384;

#pragma unroll
        for (int s = 0; s < 4; ++s) {  // 4 k16-steps per chunk
            const int kb = s * 32;     // byte offset within 128B row
            uint32_t a[4][4];
#pragma unroll
            for (int mt = 0; mt < 4; ++mt) {
                int row = wm + mt * 16 + (grp & 1) * 8 + ri;
                uint32_t addr = sa + sw128((uint32_t)(row * 128 + kb + (grp >> 1) * 16));
                LDSM_X4(a[mt], addr);
            }
            uint32_t b[2][4];
#pragma unroll
            for (int nt2 = 0; nt2 < 2; ++nt2) {
                int row = wn + nt2 * 16 + (grp >> 1) * 8 + ri;
                uint32_t addr = sb + sw128((uint32_t)(row * 128 + kb + (grp & 1) * 16));
                LDSM_X4(b[nt2], addr);
            }
#pragma unroll
            for (int mt = 0; mt < 4; ++mt)
#pragma unroll
                for (int nt = 0; nt < 4; ++nt)
                    mma16816(cfrag[mt][nt], a[mt], &b[nt >> 1][(nt & 1) * 2]);
        }

        __syncthreads();
        if (ch + 2 < NCHUNK) stage_load(ch + 2, buf);
    }

    // ---- Epilogue: masked row sums (deterministic) ----
    // d-fragment: c0,c1 -> row lane/4,  cols 2(lane%4)+{0,1}; c2,c3 -> row+8.
    float acc0[4], acc1[4];
#pragma unroll
    for (int mt = 0; mt < 4; ++mt) {
        float a0 = 0.0f, a1 = 0.0f;
        const int r0 = m0 + wm + mt * 16 + (lane >> 2);
#pragma unroll
        for (int nt = 0; nt < 4; ++nt) {
            const int ng = n0 + wn + nt * 8 + (lane & 3) * 2;
            const float* x0 = x + r0 * NDIM + ng;
            const float* x1 = x0 + 8 * NDIM;
            a0 += cfrag[mt][nt][0] * x0[0] + cfrag[mt][nt][1] * x0[1];
            a1 += cfrag[mt][nt][2] * x1[0] + cfrag[mt][nt][3] * x1[1];
        }
        a0 += __shfl_xor_sync(0xFFFFFFFF, a0, 1);
        a0 += __shfl_xor_sync(0xFFFFFFFF, a0, 2);
        a1 += __shfl_xor_sync(0xFFFFFFFF, a1, 1);
        a1 += __shfl_xor_sync(0xFFFFFFFF, a1, 2);
        acc0[mt] = a0;
        acc1[mt] = a1;
    }

    __syncthreads();  // smem stages free; reuse as reduction buffer
    float* red = reinterpret_cast<float*>(smem);  // [4 n-groups][128 rows]
    if ((lane & 3) == 0) {
        const int ng = wid & 3;
#pragma unroll
        for (int mt = 0; mt < 4; ++mt) {
            int row = wm + mt * 16 + (lane >> 2);
            red[ng * 128 + row] = acc0[mt];
            red[ng * 128 + row + 8] = acc1[mt];
        }
    }
    __syncthreads();
    if (tid < 128) {
        float p = red[tid] + red[128 + tid] + red[256 + tid] + red[384 + tid];
        g_partial[blockIdx.x * BDIM + m0 + tid] = p;
    }
}

// Deterministic final reduce over the 16 N-tile partials
__global__ void k_reduce(float* __restrict__ out) {
    int m = blockIdx.x * blockDim.x + threadIdx.x;
    float s = 0.0f;
#pragma unroll
    for (int nt = 0; nt < NT; ++nt) s += g_partial[nt * BDIM + m];
    out[m] = s;
}

// ---------------------------------------------------------------------------
extern "C" void kernel_launch(void* const* d_in, const int* in_sizes, int n_in,
                              void* d_out, int out_size) {
    const float* x = (const float*)d_in[0];  // [1024, 2048]
    const float* Q = (const float*)d_in[1];  // [2048, 2048]
    float* out = (float*)d_out;              // [1024]

    static bool attr_set = false;
    if (!attr_set) {
        cudaFuncSetAttribute(k_gemm, cudaFuncAttributeMaxDynamicSharedMemorySize,
                             SMEM_BYTES);
        attr_set = true;
    }

    k_prep_x<<<(BDIM * NDIM / 4) / 256, 256>>>(x);
    k_prep_q<<<dim3(NDIM / 32, NDIM / 32), dim3(32, 8)>>>(Q);
    k_gemm<<<dim3(NT, MT), 256, SMEM_BYTES>>>(x);
    k_reduce<<<BDIM / 256, 256>>>(out);
}